// round 1
// baseline (speedup 1.0000x reference)
#include <cuda_runtime.h>
#include <cuda_bf16.h>
#include <cstdint>

// Problem: out[m,n] = sum_k X[m,k]*W[n,k] + sum_r T[m,r]*A[n,r]
//          T[m,r]   = sum_k X[m,k]*B[r,k]
// X:[256,8192] W:[8192,8192] A:[8192,16] B:[16,8192], all f32. ALPHA=BETA=1.

#define M_TOT 256
#define N_TOT 8192
#define K_TOT 8192
#define R_LORA 16

#define BN 64
#define BK 32
#define XS_STRIDE 36   // 32 + 4 pad (floats) -> conflict-free fragment LDS

// scratch for the tiny X @ B^T intermediate (no cudaMalloc allowed)
__device__ float g_T[M_TOT * R_LORA];

// ---------------------------------------------------------------------------
// helpers
// ---------------------------------------------------------------------------
__device__ __forceinline__ unsigned f2tf32(float f) {
    unsigned u;
    asm volatile("cvt.rna.tf32.f32 %0, %1;\n" : "=r"(u) : "f"(f));
    return u;
}

__device__ __forceinline__ void cp_async16(void* smem_dst, const void* gmem_src) {
    unsigned s = (unsigned)__cvta_generic_to_shared(smem_dst);
    asm volatile("cp.async.cg.shared.global [%0], [%1], 16;\n" :: "r"(s), "l"(gmem_src));
}
__device__ __forceinline__ void cp_commit() {
    asm volatile("cp.async.commit_group;\n");
}
template <int N>
__device__ __forceinline__ void cp_wait() {
    asm volatile("cp.async.wait_group %0;\n" :: "n"(N));
}

__device__ __forceinline__ void mma_tf32(float c[4], const unsigned a[4], const unsigned b[2]) {
    asm volatile(
        "mma.sync.aligned.m16n8k8.row.col.f32.tf32.tf32.f32 "
        "{%0,%1,%2,%3}, {%4,%5,%6,%7}, {%8,%9}, {%0,%1,%2,%3};\n"
        : "+f"(c[0]), "+f"(c[1]), "+f"(c[2]), "+f"(c[3])
        : "r"(a[0]), "r"(a[1]), "r"(a[2]), "r"(a[3]), "r"(b[0]), "r"(b[1]));
}

// ---------------------------------------------------------------------------
// Kernel 1: T[m,r] = sum_k X[m,k] * B[r,k]   (exact fp32, tiny: 67 MFLOP)
// grid 64, block 256: each block owns 4 rows of X, full K, all 16 r.
// ---------------------------------------------------------------------------
__global__ __launch_bounds__(256, 1) void lora_xbt_kernel(
    const float* __restrict__ X, const float* __restrict__ Bm)
{
    __shared__ float red[8][64];
    const int tid = threadIdx.x;
    const int m0 = blockIdx.x * 4;

    float acc[4][16];
#pragma unroll
    for (int mm = 0; mm < 4; mm++)
#pragma unroll
        for (int r = 0; r < 16; r++) acc[mm][r] = 0.f;

    for (int k0 = tid * 4; k0 < K_TOT; k0 += 256 * 4) {
        float4 xv[4];
#pragma unroll
        for (int mm = 0; mm < 4; mm++)
            xv[mm] = *reinterpret_cast<const float4*>(X + (size_t)(m0 + mm) * K_TOT + k0);
#pragma unroll
        for (int r = 0; r < 16; r++) {
            float4 bv = *reinterpret_cast<const float4*>(Bm + (size_t)r * K_TOT + k0);
#pragma unroll
            for (int mm = 0; mm < 4; mm++) {
                acc[mm][r] += xv[mm].x * bv.x + xv[mm].y * bv.y +
                              xv[mm].z * bv.z + xv[mm].w * bv.w;
            }
        }
    }

    // warp reduce each of the 64 partial sums, then cross-warp via smem
#pragma unroll
    for (int mm = 0; mm < 4; mm++)
#pragma unroll
        for (int r = 0; r < 16; r++) {
            float v = acc[mm][r];
#pragma unroll
            for (int o = 16; o > 0; o >>= 1)
                v += __shfl_xor_sync(0xffffffffu, v, o);
            if ((tid & 31) == 0) red[tid >> 5][mm * 16 + r] = v;
        }
    __syncthreads();
    if (tid < 64) {
        float s = 0.f;
#pragma unroll
        for (int w = 0; w < 8; w++) s += red[w][tid];
        g_T[(size_t)(m0 + (tid >> 4)) * 16 + (tid & 15)] = s;
    }
}

// ---------------------------------------------------------------------------
// Kernel 2: main GEMM. CTA tile: M=256 (all of M) x N=64, K-loop in steps of 32.
// 128 CTAs -> W streamed from HBM exactly once (256 MB floor).
// 8 warps in 4(M) x 2(N) grid; warp tile 64x32; mma m16n8k8 tf32.
// Epilogue adds exact fp32 rank-16 LoRA term.
// smem: Xs 2*256*36 | Ws 2*64*36 | Ts 256*16 | As 64*16  = 112640 B
// ---------------------------------------------------------------------------
#define XS_BUF (256 * XS_STRIDE)
#define WS_BUF (64 * XS_STRIDE)
#define SMEM_FLOATS (2 * XS_BUF + 2 * WS_BUF + M_TOT * R_LORA + BN * R_LORA)
#define SMEM_BYTES (SMEM_FLOATS * 4)

__global__ __launch_bounds__(256, 1) void lora_gemm_kernel(
    const float* __restrict__ X, const float* __restrict__ W,
    const float* __restrict__ A, float* __restrict__ Out)
{
    extern __shared__ float smem[];
    float* Xs = smem;                        // 2 * 256*36
    float* Ws = smem + 2 * XS_BUF;           // 2 * 64*36
    float* Ts = Ws + 2 * WS_BUF;             // 256*16
    float* As = Ts + M_TOT * R_LORA;         // 64*16

    const int tid = threadIdx.x;
    const int n0 = blockIdx.x * BN;

    const int warp = tid >> 5;
    const int wm = warp >> 1;       // 0..3 (M)
    const int wn = warp & 1;        // 0..1 (N)
    const int lane = tid & 31;
    const int g = lane >> 2;        // group 0..7
    const int tig = lane & 3;       // thread-in-group 0..3

    // loader mapping (all 256 threads): 8 float4 of X, 2 float4 of W per tile
    const int c4 = (tid & 7) * 4;   // float column 0,4,...,28
    const int rr = tid >> 3;        // 0..31

    // stage LoRA operands into smem (read once, reused in epilogue)
    for (int i = tid; i < M_TOT * R_LORA; i += 256) Ts[i] = g_T[i];
    for (int i = tid; i < BN * R_LORA; i += 256) As[i] = A[(size_t)n0 * R_LORA + i];

    float c[4][4][4];
#pragma unroll
    for (int mi = 0; mi < 4; mi++)
#pragma unroll
        for (int ni = 0; ni < 4; ni++)
#pragma unroll
            for (int q = 0; q < 4; q++) c[mi][ni][q] = 0.f;

    const int NTILES = K_TOT / BK;  // 256

    // prologue: load tile 0 into buf 0
    {
        const int kt = 0;
#pragma unroll
        for (int i = 0; i < 8; i++) {
            int row = rr + 32 * i;
            cp_async16(&Xs[row * XS_STRIDE + c4], X + (size_t)row * K_TOT + kt + c4);
        }
#pragma unroll
        for (int i = 0; i < 2; i++) {
            int row = rr + 32 * i;
            cp_async16(&Ws[row * XS_STRIDE + c4], W + (size_t)(n0 + row) * K_TOT + kt + c4);
        }
        cp_commit();
    }

    for (int t = 0; t < NTILES; t++) {
        if (t + 1 < NTILES) {
            const int kt = (t + 1) * BK;
            const int buf = (t + 1) & 1;
            float* xd = Xs + buf * XS_BUF;
            float* wd = Ws + buf * WS_BUF;
#pragma unroll
            for (int i = 0; i < 8; i++) {
                int row = rr + 32 * i;
                cp_async16(&xd[row * XS_STRIDE + c4], X + (size_t)row * K_TOT + kt + c4);
            }
#pragma unroll
            for (int i = 0; i < 2; i++) {
                int row = rr + 32 * i;
                cp_async16(&wd[row * XS_STRIDE + c4], W + (size_t)(n0 + row) * K_TOT + kt + c4);
            }
            cp_commit();
            cp_wait<1>();
        } else {
            cp_wait<0>();
        }
        __syncthreads();

        const int buf = t & 1;
        const float* xb = Xs + buf * XS_BUF;
        const float* wb = Ws + buf * WS_BUF;

#pragma unroll
        for (int kk = 0; kk < BK / 8; kk++) {
            const int k = kk * 8;
            unsigned af[4][4];
            unsigned bf[4][2];
#pragma unroll
            for (int mi = 0; mi < 4; mi++) {
                int row = wm * 64 + mi * 16 + g;
                af[mi][0] = f2tf32(xb[row * XS_STRIDE + k + tig]);
                af[mi][1] = f2tf32(xb[(row + 8) * XS_STRIDE + k + tig]);
                af[mi][2] = f2tf32(xb[row * XS_STRIDE + k + tig + 4]);
                af[mi][3] = f2tf32(xb[(row + 8) * XS_STRIDE + k + tig + 4]);
            }
#pragma unroll
            for (int ni = 0; ni < 4; ni++) {
                int n = wn * 32 + ni * 8 + g;
                bf[ni][0] = f2tf32(wb[n * XS_STRIDE + k + tig]);
                bf[ni][1] = f2tf32(wb[n * XS_STRIDE + k + tig + 4]);
            }
#pragma unroll
            for (int mi = 0; mi < 4; mi++)
#pragma unroll
                for (int ni = 0; ni < 4; ni++)
                    mma_tf32(c[mi][ni], af[mi], bf[ni]);
        }
        __syncthreads();
    }

    // epilogue: exact fp32 rank-16 LoRA correction + store
#pragma unroll
    for (int mi = 0; mi < 4; mi++) {
#pragma unroll
        for (int ni = 0; ni < 4; ni++) {
            const int m = wm * 64 + mi * 16 + g;
            const int nl = wn * 32 + ni * 8 + 2 * tig;
            float d00 = 0.f, d01 = 0.f, d10 = 0.f, d11 = 0.f;
#pragma unroll
            for (int r = 0; r < R_LORA; r++) {
                float t0 = Ts[m * R_LORA + r];
                float t1 = Ts[(m + 8) * R_LORA + r];
                float a0 = As[nl * R_LORA + r];
                float a1 = As[(nl + 1) * R_LORA + r];
                d00 += t0 * a0;
                d01 += t0 * a1;
                d10 += t1 * a0;
                d11 += t1 * a1;
            }
            size_t o0 = (size_t)m * N_TOT + n0 + nl;
            float2 v0 = make_float2(c[mi][ni][0] + d00, c[mi][ni][1] + d01);
            float2 v1 = make_float2(c[mi][ni][2] + d10, c[mi][ni][3] + d11);
            *reinterpret_cast<float2*>(Out + o0) = v0;
            *reinterpret_cast<float2*>(Out + o0 + (size_t)8 * N_TOT) = v1;
        }
    }
}

// ---------------------------------------------------------------------------
extern "C" void kernel_launch(void* const* d_in, const int* in_sizes, int n_in,
                              void* d_out, int out_size)
{
    const float* x  = (const float*)d_in[0];  // [4,64,8192]
    const float* W  = (const float*)d_in[1];  // [8192,8192]
    const float* A  = (const float*)d_in[2];  // [8192,16]
    const float* Bm = (const float*)d_in[3];  // [16,8192]
    float* out = (float*)d_out;               // [4,64,8192]

    cudaFuncSetAttribute(lora_gemm_kernel,
                         cudaFuncAttributeMaxDynamicSharedMemorySize, SMEM_BYTES);

    lora_xbt_kernel<<<64, 256>>>(x, Bm);
    lora_gemm_kernel<<<N_TOT / BN, 256, SMEM_BYTES>>>(x, W, A, out);
}